// round 1
// baseline (speedup 1.0000x reference)
#include <cuda_runtime.h>
#include <math.h>

// Problem dims
#define BB 256
#define TT 512
#define FF 256
#define HH 512
#define G4 2048
#define EE 128
#define KB 8
#define NBREC 128   // persistent blocks for recurrent kernel

// ---- scratch in device globals (no allocations allowed) ----
__device__ float g_gx[(size_t)TT * BB * G4];     // [T][B][4H] input projection + biases
__device__ float g_part[(size_t)4 * BB * G4];    // split-K partials [sk][B][4H]
__device__ float g_h[BB * HH];
__device__ float g_c[BB * HH];
__device__ unsigned g_count;                     // grid barrier arrival counter

// ---------------------------------------------------------------------------
// Grid barrier: monotonic counter, reset to 0 once per launch (memsetAsync).
// Release: every thread fences (orders its global stores), then CTA sync,
// then thread 0 arrives. Acquire: thread 0 polls, fences (CCTL.IVALL flushes
// this SM's L1D on sm_103a), then CTA sync.
// ---------------------------------------------------------------------------
__device__ __forceinline__ void grid_barrier(unsigned target) {
    __threadfence();
    __syncthreads();
    if (threadIdx.x == 0) {
        atomicAdd(&g_count, 1u);
        while (atomicAdd(&g_count, 0u) < target) __nanosleep(64);
        __threadfence();
    }
    __syncthreads();
}

// ---------------------------------------------------------------------------
// 128x128 fp32 SGEMM tile, C[m][n] += sum_k A[m][k]*B[n][k] (both K-major).
// 256 threads, 8x8 per thread, KB=8 k-chunks, double-buffered smem.
// ---------------------------------------------------------------------------
__device__ __forceinline__ void sgemm_tile(
    const float* __restrict__ A, int lda,
    const float* __restrict__ Bm, int ldb,
    int m0, int n0, int k0, int nchunks,
    float (&As)[2][KB][128], float (&Bs)[2][KB][128],
    float (&acc)[8][8])
{
    const int tid = threadIdx.x;
    const int row = tid >> 1;      // 0..127
    const int seg = tid & 1;       // which half of the 8-float row chunk
    const int tx  = tid & 15;      // N-dir thread coord
    const int ty  = tid >> 4;      // M-dir thread coord

    const float* ap = A  + (size_t)(m0 + row) * lda + k0 + seg * 4;
    const float* bp = Bm + (size_t)(n0 + row) * ldb + k0 + seg * 4;

    // preload chunk 0
    float4 a4 = *(const float4*)ap;
    float4 b4 = *(const float4*)bp;
    int buf = 0;
    As[0][seg*4+0][row] = a4.x; As[0][seg*4+1][row] = a4.y;
    As[0][seg*4+2][row] = a4.z; As[0][seg*4+3][row] = a4.w;
    Bs[0][seg*4+0][row] = b4.x; Bs[0][seg*4+1][row] = b4.y;
    Bs[0][seg*4+2][row] = b4.z; Bs[0][seg*4+3][row] = b4.w;
    __syncthreads();

    for (int cc = 1; cc <= nchunks; cc++) {
        float4 na, nb;
        if (cc < nchunks) {
            na = *(const float4*)(ap + cc * KB);
            nb = *(const float4*)(bp + cc * KB);
        }
#pragma unroll
        for (int kk = 0; kk < KB; kk++) {
            float4 av0 = *(const float4*)&As[buf][kk][ty*8];
            float4 av1 = *(const float4*)&As[buf][kk][ty*8+4];
            float4 bv0 = *(const float4*)&Bs[buf][kk][tx*8];
            float4 bv1 = *(const float4*)&Bs[buf][kk][tx*8+4];
            float a[8] = {av0.x, av0.y, av0.z, av0.w, av1.x, av1.y, av1.z, av1.w};
            float b[8] = {bv0.x, bv0.y, bv0.z, bv0.w, bv1.x, bv1.y, bv1.z, bv1.w};
#pragma unroll
            for (int i = 0; i < 8; i++)
#pragma unroll
                for (int j = 0; j < 8; j++)
                    acc[i][j] = fmaf(a[i], b[j], acc[i][j]);
        }
        if (cc < nchunks) {
            buf ^= 1;
            As[buf][seg*4+0][row] = na.x; As[buf][seg*4+1][row] = na.y;
            As[buf][seg*4+2][row] = na.z; As[buf][seg*4+3][row] = na.w;
            Bs[buf][seg*4+0][row] = nb.x; Bs[buf][seg*4+1][row] = nb.y;
            Bs[buf][seg*4+2][row] = nb.z; Bs[buf][seg*4+3][row] = nb.w;
            __syncthreads();
        }
    }
}

// ---------------------------------------------------------------------------
// Phase 1: gx[t][b][:] = x[b][t][:] @ W_ih^T + (b_ih + b_hh)
// M = B*T = 131072 rows of x (row m = b*T + t), N = 4H = 2048, K = F = 256.
// ---------------------------------------------------------------------------
__global__ void __launch_bounds__(256, 1) gx_kernel(
    const float* __restrict__ x, const float* __restrict__ Wih,
    const float* __restrict__ bih, const float* __restrict__ bhh)
{
    __shared__ float As[2][KB][128];
    __shared__ float Bs[2][KB][128];
    const int n0 = blockIdx.x * 128;
    const int m0 = blockIdx.y * 128;

    float acc[8][8];
#pragma unroll
    for (int i = 0; i < 8; i++)
#pragma unroll
        for (int j = 0; j < 8; j++) acc[i][j] = 0.f;

    sgemm_tile(x, FF, Wih, FF, m0, n0, 0, FF / KB, As, Bs, acc);

    const int tx = threadIdx.x & 15, ty = threadIdx.x >> 4;
    float bias[8];
#pragma unroll
    for (int j = 0; j < 8; j++) {
        int n = n0 + tx * 8 + j;
        bias[j] = bih[n] + bhh[n];
    }
#pragma unroll
    for (int i = 0; i < 8; i++) {
        int m = m0 + ty * 8 + i;
        int t = m & (TT - 1);
        int b = m >> 9;            // T = 512 = 2^9
        float* dst = g_gx + ((size_t)t * BB + b) * G4 + n0 + tx * 8;
        float4 v0 = make_float4(acc[i][0]+bias[0], acc[i][1]+bias[1],
                                acc[i][2]+bias[2], acc[i][3]+bias[3]);
        float4 v1 = make_float4(acc[i][4]+bias[4], acc[i][5]+bias[5],
                                acc[i][6]+bias[6], acc[i][7]+bias[7]);
        *(float4*)dst       = v0;
        *(float4*)(dst + 4) = v1;
    }
}

// ---------------------------------------------------------------------------
// Phase 2: persistent recurrent kernel, 128 blocks x 256 threads.
// Per step: 32 output tiles (2 M x 16 N) x split-K 4 = 128 blocks of MMA,
// grid barrier, fused gate elementwise + h/c update, grid barrier.
// ---------------------------------------------------------------------------
__global__ void __launch_bounds__(256, 1) lstm_kernel(const float* __restrict__ Whh)
{
    __shared__ float As[2][KB][128];
    __shared__ float Bs[2][KB][128];

    const int bx = blockIdx.x;
    const int tileId = bx >> 2;
    const int sk = bx & 3;
    const int mt = tileId & 1;
    const int nt = tileId >> 1;
    const int m0 = mt * 128, n0 = nt * 128, k0 = sk * 128;

    const int tid = threadIdx.x;
    const int tx = tid & 15, ty = tid >> 4;
    const int base = bx * 256 + tid;          // 0..32767
    unsigned bars = 0;

    for (int t = 0; t < TT; t++) {
        // ---- MMA: partial = h @ W_hh^T over this block's K range ----
        float acc[8][8];
#pragma unroll
        for (int i = 0; i < 8; i++)
#pragma unroll
            for (int j = 0; j < 8; j++) acc[i][j] = 0.f;

        sgemm_tile(g_h, HH, Whh, HH, m0, n0, k0, 128 / KB, As, Bs, acc);

        float* pbase = g_part + (size_t)sk * BB * G4;
#pragma unroll
        for (int i = 0; i < 8; i++) {
            float* dst = pbase + (size_t)(m0 + ty*8 + i) * G4 + n0 + tx * 8;
            *(float4*)dst       = make_float4(acc[i][0], acc[i][1], acc[i][2], acc[i][3]);
            *(float4*)(dst + 4) = make_float4(acc[i][4], acc[i][5], acc[i][6], acc[i][7]);
        }

        bars++; grid_barrier(bars * NBREC);

        // ---- gates + state update: 131072 elems over 32768 threads ----
        const float* gxt = g_gx + (size_t)t * BB * G4;
#pragma unroll
        for (int r = 0; r < 4; r++) {
            int e = base + r * (NBREC * 256);
            int b = e >> 9;            // H = 512 = 2^9
            int j = e & (HH - 1);
            float s[4];
#pragma unroll
            for (int gi = 0; gi < 4; gi++) {
                size_t off = (size_t)b * G4 + gi * HH + j;
                float v = gxt[off];
                v += g_part[off];
                v += g_part[(size_t)1 * BB * G4 + off];
                v += g_part[(size_t)2 * BB * G4 + off];
                v += g_part[(size_t)3 * BB * G4 + off];
                s[gi] = v;
            }
            float iv = 1.f / (1.f + expf(-s[0]));
            float fv = 1.f / (1.f + expf(-s[1]));
            float gv = tanhf(s[2]);
            float ov = 1.f / (1.f + expf(-s[3]));
            float c  = fv * g_c[e] + iv * gv;
            g_c[e] = c;
            g_h[e] = ov * tanhf(c);
        }

        bars++; grid_barrier(bars * NBREC);
    }
}

// ---------------------------------------------------------------------------
// Phase 3: out[b][e] = sigmoid(hT[b][:] . W_fc[e][:] + b_fc[e])
// ---------------------------------------------------------------------------
__global__ void __launch_bounds__(128) fc_kernel(
    const float* __restrict__ Wfc, const float* __restrict__ bfc,
    float* __restrict__ out)
{
    __shared__ float hs[HH];
    const int b = blockIdx.x;
    const int tid = threadIdx.x;
    for (int k = tid; k < HH; k += 128) hs[k] = g_h[b * HH + k];
    __syncthreads();

    float acc = bfc[tid];
    const float* w = Wfc + (size_t)tid * HH;
#pragma unroll 4
    for (int k = 0; k < HH; k += 4) {
        float4 w4 = *(const float4*)(w + k);
        acc += hs[k] * w4.x + hs[k+1] * w4.y + hs[k+2] * w4.z + hs[k+3] * w4.w;
    }
    out[b * EE + tid] = 1.f / (1.f + expf(-acc));
}

// ---------------------------------------------------------------------------
extern "C" void kernel_launch(void* const* d_in, const int* in_sizes, int n_in,
                              void* d_out, int out_size) {
    const float* x   = (const float*)d_in[0];
    const float* h0  = (const float*)d_in[1];
    const float* c0  = (const float*)d_in[2];
    const float* Wih = (const float*)d_in[3];
    const float* Whh = (const float*)d_in[4];
    const float* bih = (const float*)d_in[5];
    const float* bhh = (const float*)d_in[6];
    const float* Wfc = (const float*)d_in[7];
    const float* bfc = (const float*)d_in[8];
    (void)in_sizes; (void)n_in; (void)out_size;

    // per-launch state reset (graph-capturable: async memset/memcpy only)
    void* pcount = nullptr;
    cudaGetSymbolAddress(&pcount, g_count);
    cudaMemsetAsync(pcount, 0, sizeof(unsigned), 0);
    cudaMemcpyToSymbolAsync(g_h, h0, (size_t)BB * HH * sizeof(float), 0,
                            cudaMemcpyDeviceToDevice, 0);
    cudaMemcpyToSymbolAsync(g_c, c0, (size_t)BB * HH * sizeof(float), 0,
                            cudaMemcpyDeviceToDevice, 0);

    gx_kernel<<<dim3(G4 / 128, (BB * TT) / 128), 256>>>(x, Wih, bih, bhh);
    lstm_kernel<<<NBREC, 256>>>(Whh);
    fc_kernel<<<BB, EE>>>(Wfc, bfc, (float*)d_out);
}

// round 3
// speedup vs baseline: 2.5411x; 2.5411x over previous
#include <cuda_runtime.h>
#include <cuda_bf16.h>
#include <math.h>
#include <stdint.h>

// Problem dims
#define BB 256
#define TT 512
#define FF 256
#define HH 512
#define G4 2048
#define EE 128
#define NREC 128   // persistent CTAs in recurrent kernel

// ---- device-global scratch (no allocations allowed) ----
__device__ float         g_gx[(size_t)TT * BB * G4];   // [T][B][4H] permuted-col input proj (+bias)
__device__ __nv_bfloat16 g_Wphi[(size_t)G4 * HH];      // permuted W_hh hi
__device__ __nv_bfloat16 g_Wplo[(size_t)G4 * HH];      // permuted W_hh lo
__device__ __nv_bfloat16 g_Wihphi[(size_t)G4 * FF];    // permuted W_ih hi
__device__ __nv_bfloat16 g_Wihplo[(size_t)G4 * FF];    // permuted W_ih lo
__device__ float         g_biasp[G4];                  // permuted b_ih + b_hh
__device__ __nv_bfloat16 g_hhi[BB * HH];               // h state hi
__device__ __nv_bfloat16 g_hlo[BB * HH];               // h state lo
__device__ unsigned      g_count;                      // grid barrier counter

// ---------------------------------------------------------------------------
// helpers
// ---------------------------------------------------------------------------
__device__ __forceinline__ uint32_t smem_u32(const void* p) {
    uint32_t a;
    asm("{ .reg .u64 t; cvta.to.shared.u64 t, %1; cvt.u32.u64 %0, t; }" : "=r"(a) : "l"(p));
    return a;
}
__device__ __forceinline__ float sigf(float x)   { return 1.f / (1.f + __expf(-x)); }
__device__ __forceinline__ float tanhfa(float x) { return 2.f / (1.f + __expf(-2.f * x)) - 1.f; }

// split pair of fp32 into packed bf16 hi + lo
__device__ __forceinline__ uint32_t packsplit(float a, float b, uint32_t &lo) {
    __nv_bfloat162 h = __floats2bfloat162_rn(a, b);
    __nv_bfloat162 l = __floats2bfloat162_rn(a - __low2float(h), b - __high2float(h));
    lo = reinterpret_cast<uint32_t&>(l);
    return reinterpret_cast<uint32_t&>(h);
}

__device__ __forceinline__ void ldsm4(uint32_t (&r)[4], uint32_t addr) {
    asm volatile("ldmatrix.sync.aligned.m8n8.x4.shared.b16 {%0,%1,%2,%3}, [%4];"
        : "=r"(r[0]), "=r"(r[1]), "=r"(r[2]), "=r"(r[3]) : "r"(addr));
}
__device__ __forceinline__ void mma16816(float (&c)[4], const uint32_t (&a)[4],
                                         const uint32_t b0, const uint32_t b1) {
    asm volatile("mma.sync.aligned.m16n8k16.row.col.f32.bf16.bf16.f32 "
        "{%0,%1,%2,%3}, {%4,%5,%6,%7}, {%8,%9}, {%0,%1,%2,%3};"
        : "+f"(c[0]), "+f"(c[1]), "+f"(c[2]), "+f"(c[3])
        : "r"(a[0]), "r"(a[1]), "r"(a[2]), "r"(a[3]), "r"(b0), "r"(b1));
}

__device__ __forceinline__ void grid_barrier(unsigned target) {
    __threadfence();
    __syncthreads();
    if (threadIdx.x == 0) {
        atomicAdd(&g_count, 1u);
        while (atomicAdd(&g_count, 0u) < target) __nanosleep(64);
        __threadfence();
    }
    __syncthreads();
}

// ---------------------------------------------------------------------------
// shared MMA core: one K=64 chunk for a 64-wide (NF=2) or 64-wide x2 (NF=4)
// warp tile. A chunk in smem rows of 128B (swizzled); W resident (swizzled).
// 3-term bf16 product into fp32 accumulators.
// ---------------------------------------------------------------------------
template<int NF>
__device__ __forceinline__ void mma_chunk(
    uint32_t aHi, uint32_t aLo,           // smem u32 bases of A chunk hi/lo
    uint32_t wHi, uint32_t wLo,           // smem u32 bases of resident W hi/lo
    int wRowB, int kw0,                   // W row bytes; W byte offset of chunk
    int wm, int wn, int lane,
    float (&acc)[2][NF][4])
{
    const int la  = lane & 15;
    const int aKo = (lane & 16) ? 16 : 0;
    const int nB  = wn * (NF * 8) + (lane & 7) + ((lane & 16) ? 8 : 0);
    const int bKo = (lane & 8) ? 16 : 0;
    const int m0w = wm * 32;

#pragma unroll
    for (int kk = 0; kk < 4; kk++) {
        const int kb = kk * 32;
        uint32_t ah[2][4], al[2][4];
#pragma unroll
        for (int mf = 0; mf < 2; mf++) {
            int m = m0w + mf * 16 + la;
            uint32_t off = (uint32_t)(m * 128 + ((kb + aKo) ^ ((m & 7) << 4)));
            ldsm4(ah[mf], aHi + off);
            ldsm4(al[mf], aLo + off);
        }
        uint32_t bh[NF][2], bl[NF][2];
#pragma unroll
        for (int nh = 0; nh < NF / 2; nh++) {
            int n = nB + nh * 16;
            uint32_t off = (uint32_t)(n * wRowB + ((kw0 + kb + bKo) ^ ((n & 7) << 4)));
            uint32_t r[4];
            ldsm4(r, wHi + off);
            bh[nh*2][0] = r[0]; bh[nh*2][1] = r[1];
            bh[nh*2+1][0] = r[2]; bh[nh*2+1][1] = r[3];
            ldsm4(r, wLo + off);
            bl[nh*2][0] = r[0]; bl[nh*2][1] = r[1];
            bl[nh*2+1][0] = r[2]; bl[nh*2+1][1] = r[3];
        }
#pragma unroll
        for (int mf = 0; mf < 2; mf++)
#pragma unroll
            for (int nf = 0; nf < NF; nf++) {
                mma16816(acc[mf][nf], ah[mf], bh[nf][0], bh[nf][1]);
                mma16816(acc[mf][nf], ah[mf], bl[nf][0], bl[nf][1]);
                mma16816(acc[mf][nf], al[mf], bh[nf][0], bh[nf][1]);
            }
    }
}

// ---------------------------------------------------------------------------
// prep: permute W_hh/W_ih/bias to gate-interleaved columns and split to bf16
// hi/lo. Permutation: unit j, gate (i,f,g,o)=(0..3):
//   group = j/4, q = j%4 -> cols group*16 + {2q, 2q+1, 8+2q, 9+2q}
// Also splits h0 into g_hhi/g_hlo (blocks 0..255).
// ---------------------------------------------------------------------------
__global__ void prep_kernel(const float* __restrict__ Whh, const float* __restrict__ Wih,
                            const float* __restrict__ bih, const float* __restrict__ bhh,
                            const float* __restrict__ h0)
{
    const int n = blockIdx.x;                     // permuted col 0..2047
    const int group = n >> 4, wi = n & 15;
    const int gate = ((wi >> 3) << 1) | (wi & 1);
    const int j = (group << 2) | ((wi & 7) >> 1);
    const int o = gate * HH + j;                  // original row
    const int tid = threadIdx.x;

    {   // W_hh row (512 elems, pair per thread)
        int k2 = tid * 2;
        uint32_t lo, hi = packsplit(Whh[(size_t)o * HH + k2], Whh[(size_t)o * HH + k2 + 1], lo);
        *(uint32_t*)&g_Wphi[(size_t)n * HH + k2] = hi;
        *(uint32_t*)&g_Wplo[(size_t)n * HH + k2] = lo;
    }
    if (tid < 128) {   // W_ih row (256 elems)
        int k2 = tid * 2;
        uint32_t lo, hi = packsplit(Wih[(size_t)o * FF + k2], Wih[(size_t)o * FF + k2 + 1], lo);
        *(uint32_t*)&g_Wihphi[(size_t)n * FF + k2] = hi;
        *(uint32_t*)&g_Wihplo[(size_t)n * FF + k2] = lo;
    }
    if (tid == 0) g_biasp[n] = bih[o] + bhh[o];
    if (n < BB) {      // h0 split (row n)
        int k2 = tid * 2;
        uint32_t lo, hi = packsplit(h0[(size_t)n * HH + k2], h0[(size_t)n * HH + k2 + 1], lo);
        *(uint32_t*)&g_hhi[(size_t)n * HH + k2] = hi;
        *(uint32_t*)&g_hlo[(size_t)n * HH + k2] = lo;
    }
}

// ---------------------------------------------------------------------------
// Phase 1: gx = x @ Wihp^T + biasp (permuted cols). Tile 128M x 64N, K=256.
// grid (32 n-tiles [fast], 1024 m-tiles). 8 warps: wm=w&3 (32 rows), wn=w>>2.
// smem: Whi 32KB @0, Wlo 32KB @32768, A bufs @65536 (2 x 32KB: hi16K+lo16K).
// ---------------------------------------------------------------------------
#define GX_SMEM 131072
__global__ void __launch_bounds__(256, 1) gx_kernel(const float* __restrict__ x)
{
    extern __shared__ char sm[];
    const uint32_t smu = smem_u32(sm);
    const int tid = threadIdx.x, w = tid >> 5, lane = tid & 31;
    const int wm = w & 3, wn = w >> 2;
    const int nt = blockIdx.x, m0 = blockIdx.y * 128;
    const int n0 = nt * 64;

    // load resident W (64 rows x 256 k, hi+lo): 4096 granules of 16B
#pragma unroll
    for (int i = 0; i < 16; i++) {
        int c = tid + i * 256;
        int which = c >> 11, rem = c & 2047, n = rem >> 5, g = rem & 31;
        const char* src = which ? (const char*)g_Wihplo : (const char*)g_Wihphi;
        uint4 v = *(const uint4*)(src + (size_t)(n0 + n) * 512 + g * 16);
        *(uint4*)(sm + which * 32768 + n * 512 + ((g * 16) ^ ((n & 7) << 4))) = v;
    }
    // per-thread bias (cols n0 + wn*32 + nf*8 + 2q)
    const int q = lane & 3, r = lane >> 2;
    float2 bias2[4];
#pragma unroll
    for (int nf = 0; nf < 4; nf++)
        bias2[nf] = *(const float2*)&g_biasp[n0 + wn * 32 + nf * 8 + 2 * q];
    __syncthreads();

    float acc[2][4][4];
#pragma unroll
    for (int a = 0; a < 2; a++)
#pragma unroll
        for (int b = 0; b < 4; b++)
#pragma unroll
            for (int cidx = 0; cidx < 4; cidx++) acc[a][b][cidx] = 0.f;

    uint4 shi[4], slo[4];
    // stage chunk kc into regs (split fp32 -> bf16 hi/lo)
#define GX_LD(kc) do { \
    _Pragma("unroll") \
    for (int i2 = 0; i2 < 4; i2++) { \
        int c = tid + i2 * 256; int m = c >> 3, g = c & 7; \
        const float* sp = x + (size_t)(m0 + m) * FF + (kc) * 64 + g * 8; \
        float4 f0 = *(const float4*)sp; float4 f1 = *(const float4*)(sp + 4); \
        shi[i2].x = packsplit(f0.x, f0.y, slo[i2].x); \
        shi[i2].y = packsplit(f0.z, f0.w, slo[i2].y); \
        shi[i2].z = packsplit(f1.x, f1.y, slo[i2].z); \
        shi[i2].w = packsplit(f1.z, f1.w, slo[i2].w); \
    } } while (0)
#define GX_ST(buf) do { \
    _Pragma("unroll") \
    for (int i2 = 0; i2 < 4; i2++) { \
        int c = tid + i2 * 256; int m = c >> 3, g = c & 7; \
        uint32_t off = (uint32_t)(m * 128 + ((g * 16) ^ ((m & 7) << 4))); \
        *(uint4*)(sm + 65536 + (buf) * 32768 + off) = shi[i2]; \
        *(uint4*)(sm + 65536 + (buf) * 32768 + 16384 + off) = slo[i2]; \
    } } while (0)

    GX_LD(0); GX_ST(0); __syncthreads();
#pragma unroll
    for (int kc = 0; kc < 4; kc++) {
        if (kc < 3) GX_LD(kc + 1);
        uint32_t ab = smu + 65536 + (kc & 1) * 32768;
        mma_chunk<4>(ab, ab + 16384, smu, smu + 32768, 512, kc * 128, wm, wn, lane, acc);
        if (kc < 3) { GX_ST((kc + 1) & 1); __syncthreads(); }
    }

    // epilogue: add bias, store fp32 pairs to g_gx[t][b][n']
#pragma unroll
    for (int mf = 0; mf < 2; mf++)
#pragma unroll
        for (int rp = 0; rp < 2; rp++) {
            int m = m0 + wm * 32 + mf * 16 + r + rp * 8;
            int t = m & (TT - 1), b = m >> 9;
            float* dst = g_gx + ((size_t)t * BB + b) * G4;
#pragma unroll
            for (int nf = 0; nf < 4; nf++) {
                int col = n0 + wn * 32 + nf * 8 + 2 * q;
                float2 v = make_float2(acc[mf][nf][rp*2+0] + bias2[nf].x,
                                       acc[mf][nf][rp*2+1] + bias2[nf].y);
                *(float2*)(dst + col) = v;
            }
        }
}

// ---------------------------------------------------------------------------
// Phase 2: persistent recurrent kernel. 128 CTAs x 256 threads.
// CTA bx: nt = bx>>2 (n0 = nt*64 permuted cols = units nt*16..+15),
//         mt = bx&3 (m0 = mt*64 batch rows). Tile 64x64, K=512 (8 chunks).
// 8 warps: wm = w&1, wn = w>>1 (NF=2). W resident 128KB; A dbl-buf 32KB.
// smem: Whi @0 (64KB), Wlo @65536, A @131072 (buf: hi 8KB + lo 8KB).
// ---------------------------------------------------------------------------
#define LSTM_SMEM 163840
__global__ void __launch_bounds__(256, 1) lstm_kernel(const float* __restrict__ c0)
{
    extern __shared__ char sm[];
    const uint32_t smu = smem_u32(sm);
    const int tid = threadIdx.x, w = tid >> 5, lane = tid & 31;
    const int wm = w & 1, wn = w >> 1;
    const int bx = blockIdx.x;
    const int nt = bx >> 2, mt = bx & 3;
    const int m0 = mt * 64, n0 = nt * 64;
    const int q = lane & 3, r = lane >> 2;
    const int jj = (nt * 4 + wn) * 4 + q;   // original hidden unit owned by this thread

    // load resident W (64 rows x 512 k, hi+lo): 8192 granules
#pragma unroll
    for (int i = 0; i < 32; i++) {
        int c = tid + i * 256;
        int which = c >> 12, rem = c & 4095, n = rem >> 6, g = rem & 63;
        const char* src = which ? (const char*)g_Wplo : (const char*)g_Wphi;
        uint4 v = *(const uint4*)(src + (size_t)(n0 + n) * 1024 + g * 16);
        *(uint4*)(sm + which * 65536 + n * 1024 + ((g * 16) ^ ((n & 7) << 4))) = v;
    }

    // c state in registers: 4 cells (mf, rowpair)
    float creg[4];
#pragma unroll
    for (int cell = 0; cell < 4; cell++) {
        int mf = cell >> 1, rp = cell & 1;
        int m = m0 + wm * 32 + mf * 16 + r + rp * 8;
        creg[cell] = c0[(size_t)m * HH + jj];
    }
    __syncthreads();

    uint4 stg[4];
#define LSTM_LD(kc) do { \
    _Pragma("unroll") \
    for (int i2 = 0; i2 < 4; i2++) { \
        int c = tid + i2 * 256; \
        int which = c >> 9, rem = c & 511, m = rem >> 3, g = rem & 7; \
        const char* src = which ? (const char*)g_hlo : (const char*)g_hhi; \
        stg[i2] = *(const uint4*)(src + (size_t)(m0 + m) * 1024 + (kc) * 128 + g * 16); \
    } } while (0)
#define LSTM_ST(buf) do { \
    _Pragma("unroll") \
    for (int i2 = 0; i2 < 4; i2++) { \
        int c = tid + i2 * 256; \
        int which = c >> 9, rem = c & 511, m = rem >> 3, g = rem & 7; \
        uint32_t off = (uint32_t)(m * 128 + ((g * 16) ^ ((m & 7) << 4))); \
        *(uint4*)(sm + 131072 + (buf) * 16384 + which * 8192 + off) = stg[i2]; \
    } } while (0)

    unsigned barcnt = 0;
    for (int t = 0; t < TT; t++) {
        // prefetch gx for this step's epilogue (held in regs through the mma)
        float2 gif[4], ggo[4];
#pragma unroll
        for (int cell = 0; cell < 4; cell++) {
            int mf = cell >> 1, rp = cell & 1;
            int m = m0 + wm * 32 + mf * 16 + r + rp * 8;
            const float* gp = g_gx + ((size_t)t * BB + m) * G4 + n0 + wn * 16 + 2 * q;
            gif[cell] = *(const float2*)gp;
            ggo[cell] = *(const float2*)(gp + 8);
        }

        float acc[2][2][4];
#pragma unroll
        for (int a = 0; a < 2; a++)
#pragma unroll
            for (int b = 0; b < 2; b++)
#pragma unroll
                for (int cidx = 0; cidx < 4; cidx++) acc[a][b][cidx] = 0.f;

        LSTM_LD(0); LSTM_ST(0); __syncthreads();
#pragma unroll
        for (int kc = 0; kc < 8; kc++) {
            if (kc < 7) LSTM_LD(kc + 1);
            uint32_t ab = smu + 131072 + (kc & 1) * 16384;
            mma_chunk<2>(ab, ab + 8192, smu, smu + 65536, 1024, kc * 128, wm, wn, lane, acc);
            if (kc < 7) { LSTM_ST((kc + 1) & 1); __syncthreads(); }
        }

        // epilogue: gates + state update, write h split
#pragma unroll
        for (int cell = 0; cell < 4; cell++) {
            int mf = cell >> 1, rp = cell & 1;
            float iv = sigf  (acc[mf][0][rp*2+0] + gif[cell].x);
            float fv = sigf  (acc[mf][0][rp*2+1] + gif[cell].y);
            float gv = tanhfa(acc[mf][1][rp*2+0] + ggo[cell].x);
            float ov = sigf  (acc[mf][1][rp*2+1] + ggo[cell].y);
            float cc = fv * creg[cell] + iv * gv;
            creg[cell] = cc;
            float h = ov * tanhfa(cc);
            int m = m0 + wm * 32 + mf * 16 + r + rp * 8;
            __nv_bfloat16 hi = __float2bfloat16(h);
            __nv_bfloat16 lo = __float2bfloat16(h - __bfloat162float(hi));
            g_hhi[(size_t)m * HH + jj] = hi;
            g_hlo[(size_t)m * HH + jj] = lo;
        }

        barcnt++;
        grid_barrier(barcnt * NREC);
    }
}

// ---------------------------------------------------------------------------
// Phase 3: out[b][e] = sigmoid(hT[b][:] . W_fc[e][:] + b_fc[e]); h = hi + lo
// ---------------------------------------------------------------------------
__global__ void __launch_bounds__(128) fc_kernel(
    const float* __restrict__ Wfc, const float* __restrict__ bfc,
    float* __restrict__ out)
{
    __shared__ float hs[HH];
    const int b = blockIdx.x;
    const int tid = threadIdx.x;
    for (int k = tid; k < HH; k += 128)
        hs[k] = __bfloat162float(g_hhi[(size_t)b * HH + k]) +
                __bfloat162float(g_hlo[(size_t)b * HH + k]);
    __syncthreads();

    float acc = bfc[tid];
    const float* wp = Wfc + (size_t)tid * HH;
#pragma unroll 4
    for (int k = 0; k < HH; k += 4) {
        float4 w4 = *(const float4*)(wp + k);
        acc += hs[k] * w4.x + hs[k+1] * w4.y + hs[k+2] * w4.z + hs[k+3] * w4.w;
    }
    out[b * EE + tid] = 1.f / (1.f + expf(-acc));
}

// ---------------------------------------------------------------------------
extern "C" void kernel_launch(void* const* d_in, const int* in_sizes, int n_in,
                              void* d_out, int out_size) {
    const float* x   = (const float*)d_in[0];
    const float* h0  = (const float*)d_in[1];
    const float* c0  = (const float*)d_in[2];
    const float* Wih = (const float*)d_in[3];
    const float* Whh = (const float*)d_in[4];
    const float* bih = (const float*)d_in[5];
    const float* bhh = (const float*)d_in[6];
    const float* Wfc = (const float*)d_in[7];
    const float* bfc = (const float*)d_in[8];
    (void)in_sizes; (void)n_in; (void)out_size;

    cudaFuncSetAttribute(gx_kernel,   cudaFuncAttributeMaxDynamicSharedMemorySize, GX_SMEM);
    cudaFuncSetAttribute(lstm_kernel, cudaFuncAttributeMaxDynamicSharedMemorySize, LSTM_SMEM);

    void* pcount = nullptr;
    cudaGetSymbolAddress(&pcount, g_count);
    cudaMemsetAsync(pcount, 0, sizeof(unsigned), 0);

    prep_kernel<<<G4, 256>>>(Whh, Wih, bih, bhh, h0);
    gx_kernel<<<dim3(32, 1024), 256, GX_SMEM>>>(x);
    lstm_kernel<<<NREC, 256, LSTM_SMEM>>>(c0);
    fc_kernel<<<BB, EE>>>(Wfc, bfc, (float*)d_out);
}

// round 4
// speedup vs baseline: 3.6443x; 1.4342x over previous
#include <cuda_runtime.h>
#include <cuda_bf16.h>
#include <math.h>
#include <stdint.h>

// Problem dims
#define BB 256
#define TT 512
#define FF 256
#define HH 512
#define G4 2048
#define EE 128
#define NREC 128   // persistent CTAs in recurrent kernel (4 groups of 32)

// ---- device-global scratch (no allocations allowed) ----
__device__ float         g_gx[(size_t)TT * BB * G4];   // [T][B][4H] permuted input proj (+bias)
__device__ __nv_bfloat16 g_Wphi[(size_t)G4 * HH];      // permuted W_hh hi
__device__ __nv_bfloat16 g_Wplo[(size_t)G4 * HH];      // permuted W_hh lo
__device__ __nv_bfloat16 g_Wihphi[(size_t)G4 * FF];    // permuted W_ih hi
__device__ __nv_bfloat16 g_Wihplo[(size_t)G4 * FF];    // permuted W_ih lo
__device__ float         g_biasp[G4];                  // permuted b_ih + b_hh
__device__ __nv_bfloat16 g_hhi[BB * HH];               // h state hi
__device__ __nv_bfloat16 g_hlo[BB * HH];               // h state lo (final step + h0 only)
__device__ unsigned      g_count4[128];                // 4 barrier counters, 128B apart

// ---------------------------------------------------------------------------
// helpers
// ---------------------------------------------------------------------------
__device__ __forceinline__ uint32_t smem_u32(const void* p) {
    uint32_t a;
    asm("{ .reg .u64 t; cvta.to.shared.u64 t, %1; cvt.u32.u64 %0, t; }" : "=r"(a) : "l"(p));
    return a;
}
__device__ __forceinline__ float sigf(float x)   { return 1.f / (1.f + __expf(-x)); }
__device__ __forceinline__ float tanhfa(float x) { return 2.f / (1.f + __expf(-2.f * x)) - 1.f; }

__device__ __forceinline__ uint32_t packsplit(float a, float b, uint32_t &lo) {
    __nv_bfloat162 h = __floats2bfloat162_rn(a, b);
    __nv_bfloat162 l = __floats2bfloat162_rn(a - __low2float(h), b - __high2float(h));
    lo = reinterpret_cast<uint32_t&>(l);
    return reinterpret_cast<uint32_t&>(h);
}
__device__ __forceinline__ uint32_t pack2hi(float a, float b) {
    __nv_bfloat162 h = __floats2bfloat162_rn(a, b);
    return reinterpret_cast<uint32_t&>(h);
}

__device__ __forceinline__ void ldsm4(uint32_t (&r)[4], uint32_t addr) {
    asm volatile("ldmatrix.sync.aligned.m8n8.x4.shared.b16 {%0,%1,%2,%3}, [%4];"
        : "=r"(r[0]), "=r"(r[1]), "=r"(r[2]), "=r"(r[3]) : "r"(addr));
}
__device__ __forceinline__ void mma16816(float (&c)[4], const uint32_t (&a)[4],
                                         const uint32_t b0, const uint32_t b1) {
    asm volatile("mma.sync.aligned.m16n8k16.row.col.f32.bf16.bf16.f32 "
        "{%0,%1,%2,%3}, {%4,%5,%6,%7}, {%8,%9}, {%0,%1,%2,%3};"
        : "+f"(c[0]), "+f"(c[1]), "+f"(c[2]), "+f"(c[3])
        : "r"(a[0]), "r"(a[1]), "r"(a[2]), "r"(a[3]), "r"(b0), "r"(b1));
}

// ---------------------------------------------------------------------------
// 2-term MMA for one K=64 chunk: acc += A_hi * (W_hi + W_lo)
// A single buffer (bf16 hi), rows of 128B swizzled; W resident hi/lo.
// ---------------------------------------------------------------------------
template<int NF>
__device__ __forceinline__ void mma_chunk2(
    const uint32_t aBase, const uint32_t wHi, const uint32_t wLo,
    const int wRowB, const int kw0, const int wm, const int wn, const int lane,
    float (&acc)[2][NF][4])
{
    const int la  = lane & 15;
    const int aKo = (lane & 16) ? 16 : 0;
    const int nB  = wn * (NF * 8) + (lane & 7) + ((lane & 16) ? 8 : 0);
    const int bKo = (lane & 8) ? 16 : 0;
    const int m0w = wm * 32;

#pragma unroll
    for (int kk = 0; kk < 4; kk++) {
        const int kb = kk * 32;
        uint32_t ah[2][4];
#pragma unroll
        for (int mf = 0; mf < 2; mf++) {
            int m = m0w + mf * 16 + la;
            uint32_t off = (uint32_t)(m * 128 + ((kb + aKo) ^ ((m & 7) << 4)));
            ldsm4(ah[mf], aBase + off);
        }
        uint32_t bh[NF][2], bl[NF][2];
#pragma unroll
        for (int nh = 0; nh < NF / 2; nh++) {
            int n = nB + nh * 16;
            uint32_t off = (uint32_t)(n * wRowB + ((kw0 + kb + bKo) ^ ((n & 7) << 4)));
            uint32_t r[4];
            ldsm4(r, wHi + off);
            bh[nh*2][0] = r[0]; bh[nh*2][1] = r[1];
            bh[nh*2+1][0] = r[2]; bh[nh*2+1][1] = r[3];
            ldsm4(r, wLo + off);
            bl[nh*2][0] = r[0]; bl[nh*2][1] = r[1];
            bl[nh*2+1][0] = r[2]; bl[nh*2+1][1] = r[3];
        }
#pragma unroll
        for (int mf = 0; mf < 2; mf++)
#pragma unroll
            for (int nf = 0; nf < NF; nf++) {
                mma16816(acc[mf][nf], ah[mf], bh[nf][0], bh[nf][1]);
                mma16816(acc[mf][nf], ah[mf], bl[nf][0], bl[nf][1]);
            }
    }
}

// ---------------------------------------------------------------------------
// prep: permute W_hh/W_ih/bias to gate-interleaved columns, split to bf16
// hi/lo. unit j, gate g: group=j/4, q=j%4 -> cols group*16 + {2q,2q+1,8+2q,9+2q}
// Also split h0 into g_hhi/g_hlo.
// ---------------------------------------------------------------------------
__global__ void prep_kernel(const float* __restrict__ Whh, const float* __restrict__ Wih,
                            const float* __restrict__ bih, const float* __restrict__ bhh,
                            const float* __restrict__ h0)
{
    const int n = blockIdx.x;
    const int group = n >> 4, wi = n & 15;
    const int gate = ((wi >> 3) << 1) | (wi & 1);
    const int j = (group << 2) | ((wi & 7) >> 1);
    const int o = gate * HH + j;
    const int tid = threadIdx.x;

    {
        int k2 = tid * 2;
        uint32_t lo, hi = packsplit(Whh[(size_t)o * HH + k2], Whh[(size_t)o * HH + k2 + 1], lo);
        *(uint32_t*)&g_Wphi[(size_t)n * HH + k2] = hi;
        *(uint32_t*)&g_Wplo[(size_t)n * HH + k2] = lo;
    }
    if (tid < 128) {
        int k2 = tid * 2;
        uint32_t lo, hi = packsplit(Wih[(size_t)o * FF + k2], Wih[(size_t)o * FF + k2 + 1], lo);
        *(uint32_t*)&g_Wihphi[(size_t)n * FF + k2] = hi;
        *(uint32_t*)&g_Wihplo[(size_t)n * FF + k2] = lo;
    }
    if (tid == 0) g_biasp[n] = bih[o] + bhh[o];
    if (n < BB) {
        int k2 = tid * 2;
        uint32_t lo, hi = packsplit(h0[(size_t)n * HH + k2], h0[(size_t)n * HH + k2 + 1], lo);
        *(uint32_t*)&g_hhi[(size_t)n * HH + k2] = hi;
        *(uint32_t*)&g_hlo[(size_t)n * HH + k2] = lo;
    }
}

// ---------------------------------------------------------------------------
// Phase 1: gx = x @ Wihp^T + biasp. Tile 128M x 64N per iter, 4 m-iters/CTA.
// grid (32 nt, 256 mo). 8 warps: wm=w&3, wn=w>>2 (NF=4).
// smem: Whi 32KB @0 (rowB=512), Wlo @32768, A dbl-buf @65536 (2 x 16KB, hi only)
// ---------------------------------------------------------------------------
#define GX_SMEM 98304
__global__ void __launch_bounds__(256, 1) gx_kernel(const float* __restrict__ x)
{
    extern __shared__ char sm[];
    const uint32_t smu = smem_u32(sm);
    const int tid = threadIdx.x, w = tid >> 5, lane = tid & 31;
    const int wm = w & 3, wn = w >> 2;
    const int nt = blockIdx.x;
    const int n0 = nt * 64;
    const int q = lane & 3, r = lane >> 2;

    // resident W (64 rows x 256 k, hi+lo): 4096 granules of 16B
#pragma unroll
    for (int i = 0; i < 16; i++) {
        int c = tid + i * 256;
        int which = c >> 11, rem = c & 2047, n = rem >> 5, g = rem & 31;
        const char* src = which ? (const char*)g_Wihplo : (const char*)g_Wihphi;
        uint4 v = *(const uint4*)(src + (size_t)(n0 + n) * 512 + g * 16);
        *(uint4*)(sm + which * 32768 + n * 512 + ((g * 16) ^ ((n & 7) << 4))) = v;
    }
    float2 bias2[4];
#pragma unroll
    for (int nf = 0; nf < 4; nf++)
        bias2[nf] = *(const float2*)&g_biasp[n0 + wn * 32 + nf * 8 + 2 * q];
    __syncthreads();

    uint4 shi[4];
#define GX_LD(kc, m0) do { \
    _Pragma("unroll") \
    for (int i2 = 0; i2 < 4; i2++) { \
        int c = tid + i2 * 256; int m = c >> 3, g = c & 7; \
        const float* sp = x + (size_t)((m0) + m) * FF + (kc) * 64 + g * 8; \
        float4 f0 = *(const float4*)sp; float4 f1 = *(const float4*)(sp + 4); \
        shi[i2].x = pack2hi(f0.x, f0.y); shi[i2].y = pack2hi(f0.z, f0.w); \
        shi[i2].z = pack2hi(f1.x, f1.y); shi[i2].w = pack2hi(f1.z, f1.w); \
    } } while (0)
#define GX_ST(buf) do { \
    _Pragma("unroll") \
    for (int i2 = 0; i2 < 4; i2++) { \
        int c = tid + i2 * 256; int m = c >> 3, g = c & 7; \
        *(uint4*)(sm + 65536 + (buf) * 16384 + m * 128 + ((g * 16) ^ ((m & 7) << 4))) = shi[i2]; \
    } } while (0)

    for (int it = 0; it < 4; it++) {
        const int m0 = blockIdx.y * 512 + it * 128;

        float acc[2][4][4];
#pragma unroll
        for (int a = 0; a < 2; a++)
#pragma unroll
            for (int b = 0; b < 4; b++)
#pragma unroll
                for (int cidx = 0; cidx < 4; cidx++) acc[a][b][cidx] = 0.f;

        GX_LD(0, m0); GX_ST(0); __syncthreads();
#pragma unroll
        for (int kc = 0; kc < 4; kc++) {
            if (kc < 3) GX_LD(kc + 1, m0);
            mma_chunk2<4>(smu + 65536 + (kc & 1) * 16384, smu, smu + 32768,
                          512, kc * 128, wm, wn, lane, acc);
            if (kc < 3) { GX_ST((kc + 1) & 1); __syncthreads(); }
        }

        // epilogue: add bias, store fp32 pairs to g_gx[t][b][n']
#pragma unroll
        for (int mf = 0; mf < 2; mf++)
#pragma unroll
            for (int rp = 0; rp < 2; rp++) {
                int m = m0 + wm * 32 + mf * 16 + r + rp * 8;
                int t = m & (TT - 1), b = m >> 9;
                float* dst = g_gx + ((size_t)t * BB + b) * G4;
#pragma unroll
                for (int nf = 0; nf < 4; nf++) {
                    int col = n0 + wn * 32 + nf * 8 + 2 * q;
                    *(float2*)(dst + col) =
                        make_float2(acc[mf][nf][rp*2+0] + bias2[nf].x,
                                    acc[mf][nf][rp*2+1] + bias2[nf].y);
                }
            }
        __syncthreads();   // protect A buf reuse next iter
    }
}

// ---------------------------------------------------------------------------
// Phase 2: persistent recurrent kernel. 128 CTAs x 256 threads.
// CTA bx: nt = bx>>2 (n0 = nt*64 perm cols = units nt*16..+15), mt = bx&3.
// Tile 64x64, K=512. 8 warps: wm=w&1, wn=w>>1 (NF=2).
// smem: Whi @0 (64KB, rowB=1024), Wlo @65536, A @131072 (64KB, 8 chunk blocks).
// Per-mt barrier groups of 32 CTAs. One sync in MMA phase per step.
// ---------------------------------------------------------------------------
#define LSTM_SMEM 196608
__global__ void __launch_bounds__(256, 1) lstm_kernel(const float* __restrict__ c0)
{
    extern __shared__ char sm[];
    const uint32_t smu = smem_u32(sm);
    const int tid = threadIdx.x, w = tid >> 5, lane = tid & 31;
    const int wm = w & 1, wn = w >> 1;
    const int bx = blockIdx.x;
    const int nt = bx >> 2, mt = bx & 3;
    const int m0 = mt * 64, n0 = nt * 64;
    const int q = lane & 3, r = lane >> 2;
    const int jj = (nt * 4 + wn) * 4 + q;
    unsigned* cnt = &g_count4[mt * 32];

    // resident W (64 rows x 512 k, hi+lo): 8192 granules
#pragma unroll
    for (int i = 0; i < 32; i++) {
        int c = tid + i * 256;
        int which = c >> 12, rem = c & 4095, n = rem >> 6, g = rem & 63;
        const char* src = which ? (const char*)g_Wplo : (const char*)g_Wphi;
        uint4 v = *(const uint4*)(src + (size_t)(n0 + n) * 1024 + g * 16);
        *(uint4*)(sm + which * 65536 + n * 1024 + ((g * 16) ^ ((n & 7) << 4))) = v;
    }

    float creg[4];
#pragma unroll
    for (int cell = 0; cell < 4; cell++) {
        int mf = cell >> 1, rp = cell & 1;
        int m = m0 + wm * 32 + mf * 16 + r + rp * 8;
        creg[cell] = c0[(size_t)m * HH + jj];
    }
    __syncthreads();

    // prefetch gx for t=0
    float2 gif[4], ggo[4];
#pragma unroll
    for (int cell = 0; cell < 4; cell++) {
        int mf = cell >> 1, rp = cell & 1;
        int m = m0 + wm * 32 + mf * 16 + r + rp * 8;
        const float* gp = g_gx + (size_t)m * G4 + n0 + wn * 16 + 2 * q;
        gif[cell] = *(const float2*)gp;
        ggo[cell] = *(const float2*)(gp + 8);
    }

    for (int t = 0; t < TT; t++) {
        // ---- stage whole A tile (64 rows x 512 k, h_hi): 4096 granules ----
        uint4 stg[16];
#pragma unroll
        for (int i = 0; i < 16; i++) {
            int c = tid + i * 256;
            int m = c >> 6, gi = c & 63;
            stg[i] = *(const uint4*)((const char*)g_hhi + (size_t)(m0 + m) * 1024 + gi * 16);
        }
#pragma unroll
        for (int i = 0; i < 16; i++) {
            int c = tid + i * 256;
            int m = c >> 6, gi = c & 63, kc = gi >> 3, g = gi & 7;
            *(uint4*)(sm + 131072 + kc * 8192 + m * 128 + ((g * 16) ^ ((m & 7) << 4))) = stg[i];
        }
        __syncthreads();

        // ---- MMA: 8 K-chunks, no intra-step syncs ----
        float acc[2][2][4];
#pragma unroll
        for (int a = 0; a < 2; a++)
#pragma unroll
            for (int b = 0; b < 2; b++)
#pragma unroll
                for (int cidx = 0; cidx < 4; cidx++) acc[a][b][cidx] = 0.f;
#pragma unroll
        for (int kc = 0; kc < 8; kc++)
            mma_chunk2<2>(smu + 131072 + kc * 8192, smu, smu + 65536,
                          1024, kc * 128, wm, wn, lane, acc);

        // ---- epilogue: gates + state update ----
#pragma unroll
        for (int cell = 0; cell < 4; cell++) {
            int mf = cell >> 1, rp = cell & 1;
            float iv = sigf  (acc[mf][0][rp*2+0] + gif[cell].x);
            float fv = sigf  (acc[mf][0][rp*2+1] + gif[cell].y);
            float gv = tanhfa(acc[mf][1][rp*2+0] + ggo[cell].x);
            float ov = sigf  (acc[mf][1][rp*2+1] + ggo[cell].y);
            float cc = fv * creg[cell] + iv * gv;
            creg[cell] = cc;
            float h = ov * tanhfa(cc);
            int m = m0 + wm * 32 + mf * 16 + r + rp * 8;
            __nv_bfloat16 hi = __float2bfloat16(h);
            g_hhi[(size_t)m * HH + jj] = hi;
            if (t == TT - 1)
                g_hlo[(size_t)m * HH + jj] = __float2bfloat16(h - __bfloat162float(hi));
        }

        // ---- per-mt barrier (32 CTAs); gx[t+1] prefetch between arrive/wait ----
        __threadfence();                 // CCTL.IVALL: flush L1 (all threads)
        __syncthreads();
        if (tid == 0) atomicAdd(cnt, 1u);
        if (t + 1 < TT) {
#pragma unroll
            for (int cell = 0; cell < 4; cell++) {
                int mf = cell >> 1, rp = cell & 1;
                int m = m0 + wm * 32 + mf * 16 + r + rp * 8;
                const float* gp = g_gx + ((size_t)(t + 1) * BB + m) * G4 + n0 + wn * 16 + 2 * q;
                gif[cell] = *(const float2*)gp;
                ggo[cell] = *(const float2*)(gp + 8);
            }
        }
        if (tid == 0) {
            while (atomicAdd(cnt, 0u) < (unsigned)(t + 1) * 32u) __nanosleep(32);
        }
        __syncthreads();
    }
}

// ---------------------------------------------------------------------------
// Phase 3: out[b][e] = sigmoid(hT[b][:] . W_fc[e][:] + b_fc[e]); h = hi + lo
// ---------------------------------------------------------------------------
__global__ void __launch_bounds__(128) fc_kernel(
    const float* __restrict__ Wfc, const float* __restrict__ bfc,
    float* __restrict__ out)
{
    __shared__ float hs[HH];
    const int b = blockIdx.x;
    const int tid = threadIdx.x;
    for (int k = tid; k < HH; k += 128)
        hs[k] = __bfloat162float(g_hhi[(size_t)b * HH + k]) +
                __bfloat162float(g_hlo[(size_t)b * HH + k]);
    __syncthreads();

    float acc = bfc[tid];
    const float* wp = Wfc + (size_t)tid * HH;
#pragma unroll 4
    for (int k = 0; k < HH; k += 4) {
        float4 w4 = *(const float4*)(wp + k);
        acc += hs[k] * w4.x + hs[k+1] * w4.y + hs[k+2] * w4.z + hs[k+3] * w4.w;
    }
    out[b * EE + tid] = 1.f / (1.f + expf(-acc));
}

// ---------------------------------------------------------------------------
extern "C" void kernel_launch(void* const* d_in, const int* in_sizes, int n_in,
                              void* d_out, int out_size) {
    const float* x   = (const float*)d_in[0];
    const float* h0  = (const float*)d_in[1];
    const float* c0  = (const float*)d_in[2];
    const float* Wih = (const float*)d_in[3];
    const float* Whh = (const float*)d_in[4];
    const float* bih = (const float*)d_in[5];
    const float* bhh = (const float*)d_in[6];
    const float* Wfc = (const float*)d_in[7];
    const float* bfc = (const float*)d_in[8];
    (void)in_sizes; (void)n_in; (void)out_size;

    cudaFuncSetAttribute(gx_kernel,   cudaFuncAttributeMaxDynamicSharedMemorySize, GX_SMEM);
    cudaFuncSetAttribute(lstm_kernel, cudaFuncAttributeMaxDynamicSharedMemorySize, LSTM_SMEM);

    void* pcount = nullptr;
    cudaGetSymbolAddress(&pcount, g_count4);
    cudaMemsetAsync(pcount, 0, 128 * sizeof(unsigned), 0);

    prep_kernel<<<G4, 256>>>(Whh, Wih, bih, bhh, h0);
    gx_kernel<<<dim3(32, 256), 256, GX_SMEM>>>(x);
    lstm_kernel<<<NREC, 256, LSTM_SMEM>>>(c0);
    fc_kernel<<<BB, EE>>>(Wfc, bfc, (float*)d_out);
}

// round 5
// speedup vs baseline: 3.9159x; 1.0745x over previous
#include <cuda_runtime.h>
#include <cuda_bf16.h>
#include <math.h>
#include <stdint.h>

// Problem dims
#define BB 256
#define TT 512
#define FF 256
#define HH 512
#define G4 2048
#define EE 128
#define NREC 128   // persistent CTAs in recurrent kernel (4 groups of 32)

// ---- device-global scratch (no allocations allowed) ----
__device__ float         g_gx[(size_t)TT * BB * G4];   // [T][B][4H] permuted input proj (+bias)
__device__ __nv_bfloat16 g_Wphi[(size_t)G4 * HH];      // permuted W_hh hi (bf16(W))
__device__ __nv_bfloat16 g_Wihphi[(size_t)G4 * FF];    // permuted W_ih hi
__device__ __nv_bfloat16 g_Wihplo[(size_t)G4 * FF];    // permuted W_ih lo
__device__ float         g_biasp[G4];                  // permuted b_ih + b_hh
__device__ __nv_bfloat16 g_hhi[BB * HH];               // h state hi
__device__ __nv_bfloat16 g_hlo[BB * HH];               // h state lo (h0 + final step only)
__device__ unsigned      g_count4[128];                // 4 barrier counters, 128B apart

// ---------------------------------------------------------------------------
// helpers
// ---------------------------------------------------------------------------
__device__ __forceinline__ uint32_t smem_u32(const void* p) {
    uint32_t a;
    asm("{ .reg .u64 t; cvta.to.shared.u64 t, %1; cvt.u32.u64 %0, t; }" : "=r"(a) : "l"(p));
    return a;
}
__device__ __forceinline__ float sigf(float x)   { return 1.f / (1.f + __expf(-x)); }
__device__ __forceinline__ float tanhfa(float x) { return 2.f / (1.f + __expf(-2.f * x)) - 1.f; }

__device__ __forceinline__ uint32_t packsplit(float a, float b, uint32_t &lo) {
    __nv_bfloat162 h = __floats2bfloat162_rn(a, b);
    __nv_bfloat162 l = __floats2bfloat162_rn(a - __low2float(h), b - __high2float(h));
    lo = reinterpret_cast<uint32_t&>(l);
    return reinterpret_cast<uint32_t&>(h);
}
__device__ __forceinline__ uint32_t pack2hi(float a, float b) {
    __nv_bfloat162 h = __floats2bfloat162_rn(a, b);
    return reinterpret_cast<uint32_t&>(h);
}

__device__ __forceinline__ void ldsm4(uint32_t (&r)[4], uint32_t addr) {
    asm volatile("ldmatrix.sync.aligned.m8n8.x4.shared.b16 {%0,%1,%2,%3}, [%4];"
        : "=r"(r[0]), "=r"(r[1]), "=r"(r[2]), "=r"(r[3]) : "r"(addr));
}
__device__ __forceinline__ void mma16816(float (&c)[4], const uint32_t (&a)[4],
                                         const uint32_t b0, const uint32_t b1) {
    asm volatile("mma.sync.aligned.m16n8k16.row.col.f32.bf16.bf16.f32 "
        "{%0,%1,%2,%3}, {%4,%5,%6,%7}, {%8,%9}, {%0,%1,%2,%3};"
        : "+f"(c[0]), "+f"(c[1]), "+f"(c[2]), "+f"(c[3])
        : "r"(a[0]), "r"(a[1]), "r"(a[2]), "r"(a[3]), "r"(b0), "r"(b1));
}

// ---------------------------------------------------------------------------
// 2-term MMA chunk (gx): acc += A_hi * (W_hi + W_lo). NF n-fragments.
// ---------------------------------------------------------------------------
template<int NF>
__device__ __forceinline__ void mma_chunk2(
    const uint32_t aBase, const uint32_t wHi, const uint32_t wLo,
    const int wRowB, const int kw0, const int wm, const int wn, const int lane,
    float (&acc)[2][NF][4])
{
    const int la  = lane & 15;
    const int aKo = (lane & 16) ? 16 : 0;
    const int nB  = wn * (NF * 8) + (lane & 7) + ((lane & 16) ? 8 : 0);
    const int bKo = (lane & 8) ? 16 : 0;
    const int m0w = wm * 32;

#pragma unroll
    for (int kk = 0; kk < 4; kk++) {
        const int kb = kk * 32;
        uint32_t ah[2][4];
#pragma unroll
        for (int mf = 0; mf < 2; mf++) {
            int m = m0w + mf * 16 + la;
            uint32_t off = (uint32_t)(m * 128 + ((kb + aKo) ^ ((m & 7) << 4)));
            ldsm4(ah[mf], aBase + off);
        }
        uint32_t bh[NF][2], bl[NF][2];
#pragma unroll
        for (int nh = 0; nh < NF / 2; nh++) {
            int n = nB + nh * 16;
            uint32_t off = (uint32_t)(n * wRowB + ((kw0 + kb + bKo) ^ ((n & 7) << 4)));
            uint32_t r[4];
            ldsm4(r, wHi + off);
            bh[nh*2][0] = r[0]; bh[nh*2][1] = r[1];
            bh[nh*2+1][0] = r[2]; bh[nh*2+1][1] = r[3];
            ldsm4(r, wLo + off);
            bl[nh*2][0] = r[0]; bl[nh*2][1] = r[1];
            bl[nh*2+1][0] = r[2]; bl[nh*2+1][1] = r[3];
        }
#pragma unroll
        for (int mf = 0; mf < 2; mf++)
#pragma unroll
            for (int nf = 0; nf < NF; nf++) {
                mma16816(acc[mf][nf], ah[mf], bh[nf][0], bh[nf][1]);
                mma16816(acc[mf][nf], ah[mf], bl[nf][0], bl[nf][1]);
            }
    }
}

// ---------------------------------------------------------------------------
// 1-term MMA chunk (recurrence): acc += A_hi * W_hi. NF=2.
// ---------------------------------------------------------------------------
__device__ __forceinline__ void mma_chunk1(
    const uint32_t aBase, const uint32_t wHi,
    const int wRowB, const int kw0, const int wm, const int wn, const int lane,
    float (&acc)[2][2][4])
{
    const int la  = lane & 15;
    const int aKo = (lane & 16) ? 16 : 0;
    const int nB  = wn * 16 + (lane & 7) + ((lane & 16) ? 8 : 0);
    const int bKo = (lane & 8) ? 16 : 0;
    const int m0w = wm * 32;

#pragma unroll
    for (int kk = 0; kk < 4; kk++) {
        const int kb = kk * 32;
        uint32_t ah[2][4];
#pragma unroll
        for (int mf = 0; mf < 2; mf++) {
            int m = m0w + mf * 16 + la;
            uint32_t off = (uint32_t)(m * 128 + ((kb + aKo) ^ ((m & 7) << 4)));
            ldsm4(ah[mf], aBase + off);
        }
        uint32_t r[4];
        {
            int n = nB;
            uint32_t off = (uint32_t)(n * wRowB + ((kw0 + kb + bKo) ^ ((n & 7) << 4)));
            ldsm4(r, wHi + off);
        }
#pragma unroll
        for (int mf = 0; mf < 2; mf++) {
            mma16816(acc[mf][0], ah[mf], r[0], r[1]);
            mma16816(acc[mf][1], ah[mf], r[2], r[3]);
        }
    }
}

// ---------------------------------------------------------------------------
// prep: permute W_hh/W_ih/bias to gate-interleaved columns.
// unit j, gate g: group=j/4, q=j%4 -> cols group*16 + {2q,2q+1,8+2q,9+2q}
// W_hh stored as single bf16 (hi); W_ih split hi/lo. h0 split hi/lo.
// ---------------------------------------------------------------------------
__global__ void prep_kernel(const float* __restrict__ Whh, const float* __restrict__ Wih,
                            const float* __restrict__ bih, const float* __restrict__ bhh,
                            const float* __restrict__ h0)
{
    const int n = blockIdx.x;
    const int group = n >> 4, wi = n & 15;
    const int gate = ((wi >> 3) << 1) | (wi & 1);
    const int j = (group << 2) | ((wi & 7) >> 1);
    const int o = gate * HH + j;
    const int tid = threadIdx.x;

    {
        int k2 = tid * 2;
        uint32_t hi = pack2hi(Whh[(size_t)o * HH + k2], Whh[(size_t)o * HH + k2 + 1]);
        *(uint32_t*)&g_Wphi[(size_t)n * HH + k2] = hi;
    }
    if (tid < 128) {
        int k2 = tid * 2;
        uint32_t lo, hi = packsplit(Wih[(size_t)o * FF + k2], Wih[(size_t)o * FF + k2 + 1], lo);
        *(uint32_t*)&g_Wihphi[(size_t)n * FF + k2] = hi;
        *(uint32_t*)&g_Wihplo[(size_t)n * FF + k2] = lo;
    }
    if (tid == 0) g_biasp[n] = bih[o] + bhh[o];
    if (n < BB) {
        int k2 = tid * 2;
        uint32_t lo, hi = packsplit(h0[(size_t)n * HH + k2], h0[(size_t)n * HH + k2 + 1], lo);
        *(uint32_t*)&g_hhi[(size_t)n * HH + k2] = hi;
        *(uint32_t*)&g_hlo[(size_t)n * HH + k2] = lo;
    }
}

// ---------------------------------------------------------------------------
// Phase 1: gx = x @ Wihp^T + biasp. Tile 128M x 64N per iter, 4 m-iters/CTA.
// grid (32 nt, 256 mo). 8 warps: wm=w&3, wn=w>>2 (NF=4). 2-term.
// smem: Whi 32KB @0 (rowB=512), Wlo @32768, A dbl-buf @65536 (2 x 16KB)
// ---------------------------------------------------------------------------
#define GX_SMEM 98304
__global__ void __launch_bounds__(256, 1) gx_kernel(const float* __restrict__ x)
{
    extern __shared__ char sm[];
    const uint32_t smu = smem_u32(sm);
    const int tid = threadIdx.x, w = tid >> 5, lane = tid & 31;
    const int wm = w & 3, wn = w >> 2;
    const int nt = blockIdx.x;
    const int n0 = nt * 64;
    const int q = lane & 3, r = lane >> 2;

#pragma unroll
    for (int i = 0; i < 16; i++) {
        int c = tid + i * 256;
        int which = c >> 11, rem = c & 2047, n = rem >> 5, g = rem & 31;
        const char* src = which ? (const char*)g_Wihplo : (const char*)g_Wihphi;
        uint4 v = *(const uint4*)(src + (size_t)(n0 + n) * 512 + g * 16);
        *(uint4*)(sm + which * 32768 + n * 512 + ((g * 16) ^ ((n & 7) << 4))) = v;
    }
    float2 bias2[4];
#pragma unroll
    for (int nf = 0; nf < 4; nf++)
        bias2[nf] = *(const float2*)&g_biasp[n0 + wn * 32 + nf * 8 + 2 * q];
    __syncthreads();

    uint4 shi[4];
#define GX_LD(kc, m0) do { \
    _Pragma("unroll") \
    for (int i2 = 0; i2 < 4; i2++) { \
        int c = tid + i2 * 256; int m = c >> 3, g = c & 7; \
        const float* sp = x + (size_t)((m0) + m) * FF + (kc) * 64 + g * 8; \
        float4 f0 = *(const float4*)sp; float4 f1 = *(const float4*)(sp + 4); \
        shi[i2].x = pack2hi(f0.x, f0.y); shi[i2].y = pack2hi(f0.z, f0.w); \
        shi[i2].z = pack2hi(f1.x, f1.y); shi[i2].w = pack2hi(f1.z, f1.w); \
    } } while (0)
#define GX_ST(buf) do { \
    _Pragma("unroll") \
    for (int i2 = 0; i2 < 4; i2++) { \
        int c = tid + i2 * 256; int m = c >> 3, g = c & 7; \
        *(uint4*)(sm + 65536 + (buf) * 16384 + m * 128 + ((g * 16) ^ ((m & 7) << 4))) = shi[i2]; \
    } } while (0)

    for (int it = 0; it < 4; it++) {
        const int m0 = blockIdx.y * 512 + it * 128;

        float acc[2][4][4];
#pragma unroll
        for (int a = 0; a < 2; a++)
#pragma unroll
            for (int b = 0; b < 4; b++)
#pragma unroll
                for (int cidx = 0; cidx < 4; cidx++) acc[a][b][cidx] = 0.f;

        GX_LD(0, m0); GX_ST(0); __syncthreads();
#pragma unroll
        for (int kc = 0; kc < 4; kc++) {
            if (kc < 3) GX_LD(kc + 1, m0);
            mma_chunk2<4>(smu + 65536 + (kc & 1) * 16384, smu, smu + 32768,
                          512, kc * 128, wm, wn, lane, acc);
            if (kc < 3) { GX_ST((kc + 1) & 1); __syncthreads(); }
        }

#pragma unroll
        for (int mf = 0; mf < 2; mf++)
#pragma unroll
            for (int rp = 0; rp < 2; rp++) {
                int m = m0 + wm * 32 + mf * 16 + r + rp * 8;
                int t = m & (TT - 1), b = m >> 9;
                float* dst = g_gx + ((size_t)t * BB + b) * G4;
#pragma unroll
                for (int nf = 0; nf < 4; nf++) {
                    int col = n0 + wn * 32 + nf * 8 + 2 * q;
                    *(float2*)(dst + col) =
                        make_float2(acc[mf][nf][rp*2+0] + bias2[nf].x,
                                    acc[mf][nf][rp*2+1] + bias2[nf].y);
                }
            }
        __syncthreads();
    }
}

// ---------------------------------------------------------------------------
// Phase 2: persistent recurrent kernel. 128 CTAs x 256 threads, 1-term MMA.
// CTA bx: nt = bx>>2 (n0 = nt*64 perm cols), mt = bx&3 (m0 = mt*64 rows).
// smem: W @0 (64KB, rowB=1024), A @65536 (64KB, 8 chunk blocks of 8KB).
// Per-mt barrier (32 CTAs), one-thread release/acquire; staged/MMA overlap.
// ---------------------------------------------------------------------------
#define LSTM_SMEM 131072
__global__ void __launch_bounds__(256, 1) lstm_kernel(const float* __restrict__ c0)
{
    extern __shared__ char sm[];
    const uint32_t smu = smem_u32(sm);
    const int tid = threadIdx.x, w = tid >> 5, lane = tid & 31;
    const int wm = w & 1, wn = w >> 1;
    const int bx = blockIdx.x;
    const int nt = bx >> 2, mt = bx & 3;
    const int m0 = mt * 64, n0 = nt * 64;
    const int q = lane & 3, r = lane >> 2;
    const int jj = (nt * 4 + wn) * 4 + q;
    const int kc_self = (tid & 63) >> 3;     // the single kc this thread stages
    unsigned* cnt = &g_count4[mt * 32];

    // resident W (64 rows x 512 k, bf16): 4096 granules of 16B
#pragma unroll
    for (int i = 0; i < 16; i++) {
        int c = tid + i * 256;
        int n = c >> 6, g = c & 63;
        uint4 v = *(const uint4*)((const char*)g_Wphi + (size_t)(n0 + n) * 1024 + g * 16);
        *(uint4*)(sm + n * 1024 + ((g * 16) ^ ((n & 7) << 4))) = v;
    }

    float creg[4];
#pragma unroll
    for (int cell = 0; cell < 4; cell++) {
        int mf = cell >> 1, rp = cell & 1;
        int m = m0 + wm * 32 + mf * 16 + r + rp * 8;
        creg[cell] = c0[(size_t)m * HH + jj];
    }
    __syncthreads();

    // prefetch gx for t=0
    float2 gif[4], ggo[4];
#pragma unroll
    for (int cell = 0; cell < 4; cell++) {
        int mf = cell >> 1, rp = cell & 1;
        int m = m0 + wm * 32 + mf * 16 + r + rp * 8;
        const float* gp = g_gx + (size_t)m * G4 + n0 + wn * 16 + 2 * q;
        gif[cell] = *(const float2*)gp;
        ggo[cell] = *(const float2*)(gp + 8);
    }

    for (int t = 0; t < TT; t++) {
        // ---- stage A tile (64 rows x 512 k of h_hi) via L2, overlap w/ MMA ----
        uint4 stg[16];
#pragma unroll
        for (int i = 0; i < 16; i++) {
            int c = tid + i * 256;
            int m = c >> 6, gi = c & 63;
            stg[i] = __ldcg((const uint4*)((const char*)g_hhi + (size_t)(m0 + m) * 1024 + gi * 16));
        }
        if (kc_self < 4) {
#pragma unroll
            for (int i = 0; i < 16; i++) {
                int c = tid + i * 256;
                int m = c >> 6, gi = c & 63, kc = gi >> 3, g = gi & 7;
                *(uint4*)(sm + 65536 + kc * 8192 + m * 128 + ((g * 16) ^ ((m & 7) << 4))) = stg[i];
            }
        }
        __syncthreads();
        if (kc_self >= 4) {
#pragma unroll
            for (int i = 0; i < 16; i++) {
                int c = tid + i * 256;
                int m = c >> 6, gi = c & 63, kc = gi >> 3, g = gi & 7;
                *(uint4*)(sm + 65536 + kc * 8192 + m * 128 + ((g * 16) ^ ((m & 7) << 4))) = stg[i];
            }
        }

        float acc[2][2][4];
#pragma unroll
        for (int a = 0; a < 2; a++)
#pragma unroll
            for (int b = 0; b < 2; b++)
#pragma unroll
                for (int cidx = 0; cidx < 4; cidx++) acc[a][b][cidx] = 0.f;

#pragma unroll
        for (int kc = 0; kc < 4; kc++)          // chunks 0-3 (overlaps STS of 4-7)
            mma_chunk1(smu + 65536 + kc * 8192, smu, 1024, kc * 128, wm, wn, lane, acc);
        __syncthreads();
#pragma unroll
        for (int kc = 4; kc < 8; kc++)          // chunks 4-7
            mma_chunk1(smu + 65536 + kc * 8192, smu, 1024, kc * 128, wm, wn, lane, acc);

        // ---- epilogue: gates + state update ----
#pragma unroll
        for (int cell = 0; cell < 4; cell++) {
            int mf = cell >> 1, rp = cell & 1;
            float iv = sigf  (acc[mf][0][rp*2+0] + gif[cell].x);
            float fv = sigf  (acc[mf][0][rp*2+1] + gif[cell].y);
            float gv = tanhfa(acc[mf][1][rp*2+0] + ggo[cell].x);
            float ov = sigf  (acc[mf][1][rp*2+1] + ggo[cell].y);
            float cc = fv * creg[cell] + iv * gv;
            creg[cell] = cc;
            float h = ov * tanhfa(cc);
            int m = m0 + wm * 32 + mf * 16 + r + rp * 8;
            __nv_bfloat16 hi = __float2bfloat16(h);
            g_hhi[(size_t)m * HH + jj] = hi;
            if (t == TT - 1)
                g_hlo[(size_t)m * HH + jj] = __float2bfloat16(h - __bfloat162float(hi));
        }

        // ---- per-mt barrier: one-thread release/acquire; prefetch in window ----
        __syncthreads();
        if (tid == 0) {
            asm volatile("fence.acq_rel.gpu;" ::: "memory");
            atomicAdd(cnt, 1u);
        }
        if (t + 1 < TT) {
#pragma unroll
            for (int cell = 0; cell < 4; cell++) {
                int mf = cell >> 1, rp = cell & 1;
                int m = m0 + wm * 32 + mf * 16 + r + rp * 8;
                const float* gp = g_gx + ((size_t)(t + 1) * BB + m) * G4 + n0 + wn * 16 + 2 * q;
                gif[cell] = *(const float2*)gp;
                ggo[cell] = *(const float2*)(gp + 8);
            }
        }
        if (tid == 0) {
            while (atomicAdd(cnt, 0u) < (unsigned)(t + 1) * 32u) __nanosleep(32);
            asm volatile("fence.acq_rel.gpu;" ::: "memory");
        }
        __syncthreads();
    }
}

// ---------------------------------------------------------------------------
// Phase 3: out[b][e] = sigmoid(hT[b][:] . W_fc[e][:] + b_fc[e]); h = hi + lo
// grid 32 x 256 threads; 8 batches per block (thread: e = tid&127, 4 b's)
// ---------------------------------------------------------------------------
__global__ void __launch_bounds__(256) fc_kernel(
    const float* __restrict__ Wfc, const float* __restrict__ bfc,
    float* __restrict__ out)
{
    __shared__ float hs[8][HH];
    const int bg = blockIdx.x;         // batches bg*8 .. bg*8+7
    const int tid = threadIdx.x;
    for (int idx = tid; idx < 8 * HH; idx += 256) {
        int b = idx >> 9, k = idx & (HH - 1);
        size_t off = (size_t)(bg * 8 + b) * HH + k;
        hs[b][k] = __bfloat162float(g_hhi[off]) + __bfloat162float(g_hlo[off]);
    }
    __syncthreads();

    const int e = tid & 127, half = tid >> 7;   // half: batches 0-3 or 4-7
    float acc[4];
#pragma unroll
    for (int bb = 0; bb < 4; bb++) acc[bb] = bfc[e];
    const float* wp = Wfc + (size_t)e * HH;
#pragma unroll 4
    for (int k = 0; k < HH; k += 4) {
        float4 w4 = *(const float4*)(wp + k);
#pragma unroll
        for (int bb = 0; bb < 4; bb++) {
            const float* h4 = &hs[half * 4 + bb][k];
            acc[bb] += h4[0] * w4.x + h4[1] * w4.y + h4[2] * w4.z + h4[3] * w4.w;
        }
    }
#pragma unroll
    for (int bb = 0; bb < 4; bb++)
        out[(size_t)(bg * 8 + half * 4 + bb) * EE + e] = sigf(acc[bb]);
}

// ---------------------------------------------------------------------------
extern "C" void kernel_launch(void* const* d_in, const int* in_sizes, int n_in,
                              void* d_out, int out_size) {
    const float* x   = (const float*)d_in[0];
    const float* h0  = (const float*)d_in[1];
    const float* c0  = (const float*)d_in[2];
    const float* Wih = (const float*)d_in[3];
    const float* Whh = (const float*)d_in[4];
    const float* bih = (const float*)d_in[5];
    const float* bhh = (const float*)d_in[6];
    const float* Wfc = (const float*)d_in[7];
    const float* bfc = (const float*)d_in[8];
    (void)in_sizes; (void)n_in; (void)out_size;

    cudaFuncSetAttribute(gx_kernel,   cudaFuncAttributeMaxDynamicSharedMemorySize, GX_SMEM);
    cudaFuncSetAttribute(lstm_kernel, cudaFuncAttributeMaxDynamicSharedMemorySize, LSTM_SMEM);

    void* pcount = nullptr;
    cudaGetSymbolAddress(&pcount, g_count4);
    cudaMemsetAsync(pcount, 0, 128 * sizeof(unsigned), 0);

    prep_kernel<<<G4, 256>>>(Whh, Wih, bih, bhh, h0);
    gx_kernel<<<dim3(32, 256), 256, GX_SMEM>>>(x);
    lstm_kernel<<<NREC, 256, LSTM_SMEM>>>(c0);
    fc_kernel<<<32, 256>>>(Wfc, bfc, (float*)d_out);
}